// round 3
// baseline (speedup 1.0000x reference)
#include <cuda_runtime.h>
#include <math.h>
#include <stdint.h>

// Problem constants
#define B_   16
#define L_   512
#define H_   1024
#define HS   64     // HEAD_SIZE
#define NH   12     // HEADS
#define INFV 1000000000000.0f

// Scratch (allocation-free rule: __device__ globals)
__device__ __align__(16) float g_qwT[B_ * HS * L_];          // 2 MB  [b][d][l]
__device__ __align__(16) float g_kwT[B_ * HS * L_];          // 2 MB  [b][d][l]
__device__ __align__(16) float g_bias[B_ * 2 * NH * L_];     // 768 KB [b][j][l]

// ---------------------------------------------------------------------------
// mma.sync m16n8k8 tf32 wrapper (fp32 bits passed as tf32; fp32 accumulate)
// ---------------------------------------------------------------------------
__device__ __forceinline__ void mma_tf32(
    float& c0, float& c1, float& c2, float& c3,
    uint32_t a0, uint32_t a1, uint32_t a2, uint32_t a3,
    uint32_t b0, uint32_t b1)
{
    asm volatile(
        "mma.sync.aligned.m16n8k8.row.col.f32.tf32.tf32.f32 "
        "{%0,%1,%2,%3}, {%4,%5,%6,%7}, {%8,%9}, {%0,%1,%2,%3};"
        : "+f"(c0), "+f"(c1), "+f"(c2), "+f"(c3)
        : "r"(a0), "r"(a1), "r"(a2), "r"(a3), "r"(b0), "r"(b1));
}

// ---------------------------------------------------------------------------
// Kernel A v2: x = inputs@W1 + b1 via TF32 tensor-core MMA.
//   64(M) x 128(N) tile per block, K=1024, K-chunk=32, double-buffered smem.
//   Operands stored in smem in FRAGMENT-PERMUTED layout:
//     As[stage][kstep(4)][mtile(4)][lane(32)][4]  -> consumer lds.128
//     Bs[stage][kstep(4)][ntile(16)][lane(32)][2] -> consumer lds.64
//   Epilogue: RoPE -> g_qwT/g_kwT (transposed), bias GEMV -> g_bias.
// grid 128 blocks, 256 threads (8 warps: 2(M) x 4(N), each 32x32).
// ---------------------------------------------------------------------------
__global__ __launch_bounds__(256) void proj_kernel(
    const float* __restrict__ inp, const float* __restrict__ W1,
    const float* __restrict__ b1,  const float* __restrict__ W2,
    const float* __restrict__ b2)
{
    // pool: 2 stages x (2048 A floats + 4096 B floats) = 12288 floats = 48KB.
    // Reused after the mainloop as xs[64][132] (8448 floats).
    __shared__ __align__(16) float pool[12288];

    const int tid  = threadIdx.x;
    const int lane = tid & 31;
    const int warp = tid >> 5;
    const int wm   = warp >> 2;    // 0..1
    const int wn   = warp & 3;     // 0..3
    const int gId  = lane >> 2;    // groupID
    const int tig  = lane & 3;     // threadID_in_group
    const int m0   = blockIdx.x * 64;

    // ---- global load assignments (per 32-K stage) ----
    const int am[2]  = { (tid + 0)   >> 3, (tid + 256) >> 3 };
    const int akq[2] = { (tid + 0)   & 7,  (tid + 256) & 7  };
    int bk[4], bnq[4];
    #pragma unroll
    for (int j = 0; j < 4; j++) { int f = tid + 256 * j; bk[j] = f >> 5; bnq[j] = f & 31; }

    const float* aptr0 = inp + (size_t)(m0 + am[0]) * H_ + akq[0] * 4;
    const float* aptr1 = inp + (size_t)(m0 + am[1]) * H_ + akq[1] * 4;

    // ---- precompute smem scatter offsets (stage-relative, in floats) ----
    int a_off[2][4];
    #pragma unroll
    for (int j = 0; j < 2; j++) {
        int m = am[j], mt = m >> 4, r = m & 15, g = r & 7;
        #pragma unroll
        for (int e = 0; e < 4; e++) {
            int k = akq[j] * 4 + e;
            int ks = k >> 3;
            int reg = ((r >> 3) & 1) + ((k & 4) ? 2 : 0);
            int ln  = g * 4 + (k & 3);
            a_off[j][e] = ((ks * 4 + mt) * 32 + ln) * 4 + reg;
        }
    }
    int b_off[4][4];
    #pragma unroll
    for (int j = 0; j < 4; j++) {
        int k = bk[j], ks = k >> 3, reg = (k & 4) ? 1 : 0, kl = k & 3;
        #pragma unroll
        for (int e = 0; e < 4; e++) {
            int n = bnq[j] * 4 + e;
            b_off[j][e] = ((ks * 16 + (n >> 3)) * 32 + ((n & 7) * 4 + kl)) * 2 + reg;
        }
    }

    // ---- consumer fragment base offsets ----
    int afrag_off[2];
    #pragma unroll
    for (int mt = 0; mt < 2; mt++)
        afrag_off[mt] = ((wm * 2 + mt) * 32 + lane) * 4;
    int bfrag_off[4];
    #pragma unroll
    for (int nt = 0; nt < 4; nt++)
        bfrag_off[nt] = ((wn * 4 + nt) * 32 + lane) * 2;

    float acc[2][4][4];
    #pragma unroll
    for (int mt = 0; mt < 2; mt++)
        #pragma unroll
        for (int nt = 0; nt < 4; nt++)
            #pragma unroll
            for (int c = 0; c < 4; c++) acc[mt][nt][c] = 0.f;

    // ---- prologue loads (stage 0) ----
    float4 pa[2], pb[4];
    pa[0] = *(const float4*)aptr0;
    pa[1] = *(const float4*)aptr1;
    #pragma unroll
    for (int j = 0; j < 4; j++)
        pb[j] = *(const float4*)(W1 + (size_t)bk[j] * 128 + bnq[j] * 4);

    for (int kt = 0; kt < 32; kt++) {
        float* As = pool + (kt & 1) * 6144;
        float* Bs = As + 2048;
        __syncthreads();
        #pragma unroll
        for (int j = 0; j < 2; j++) {
            As[a_off[j][0]] = pa[j].x; As[a_off[j][1]] = pa[j].y;
            As[a_off[j][2]] = pa[j].z; As[a_off[j][3]] = pa[j].w;
        }
        #pragma unroll
        for (int j = 0; j < 4; j++) {
            Bs[b_off[j][0]] = pb[j].x; Bs[b_off[j][1]] = pb[j].y;
            Bs[b_off[j][2]] = pb[j].z; Bs[b_off[j][3]] = pb[j].w;
        }
        __syncthreads();
        if (kt < 31) {
            int k0n = (kt + 1) * 32;
            pa[0] = *(const float4*)(aptr0 + k0n);
            pa[1] = *(const float4*)(aptr1 + k0n);
            #pragma unroll
            for (int j = 0; j < 4; j++)
                pb[j] = *(const float4*)(W1 + (size_t)(k0n + bk[j]) * 128 + bnq[j] * 4);
        }
        #pragma unroll
        for (int ks = 0; ks < 4; ks++) {
            uint32_t af[2][4];
            #pragma unroll
            for (int mt = 0; mt < 2; mt++) {
                float4 v = *(const float4*)&As[ks * 512 + afrag_off[mt]];
                af[mt][0] = __float_as_uint(v.x); af[mt][1] = __float_as_uint(v.y);
                af[mt][2] = __float_as_uint(v.z); af[mt][3] = __float_as_uint(v.w);
            }
            uint32_t bf[4][2];
            #pragma unroll
            for (int nt = 0; nt < 4; nt++) {
                float2 v = *(const float2*)&Bs[ks * 1024 + bfrag_off[nt]];
                bf[nt][0] = __float_as_uint(v.x); bf[nt][1] = __float_as_uint(v.y);
            }
            #pragma unroll
            for (int mt = 0; mt < 2; mt++)
                #pragma unroll
                for (int nt = 0; nt < 4; nt++)
                    mma_tf32(acc[mt][nt][0], acc[mt][nt][1], acc[mt][nt][2], acc[mt][nt][3],
                             af[mt][0], af[mt][1], af[mt][2], af[mt][3],
                             bf[nt][0], bf[nt][1]);
        }
    }

    __syncthreads();   // done reading pipeline smem; reuse pool as xs

    float (*xs)[132] = (float (*)[132])pool;

    // ---- write acc (+b1) into xs ----
    #pragma unroll
    for (int mt = 0; mt < 2; mt++) {
        int mrow = wm * 32 + mt * 16 + gId;
        #pragma unroll
        for (int nt = 0; nt < 4; nt++) {
            int n = wn * 32 + nt * 8 + tig * 2;
            float2 bb = *(const float2*)(b1 + n);
            xs[mrow][n]         = acc[mt][nt][0] + bb.x;
            xs[mrow][n + 1]     = acc[mt][nt][1] + bb.y;
            xs[mrow + 8][n]     = acc[mt][nt][2] + bb.x;
            xs[mrow + 8][n + 1] = acc[mt][nt][3] + bb.y;
        }
    }
    __syncthreads();

    const int bb_ = m0 >> 9;    // batch
    const int l0  = m0 & 511;   // sequence offset of tile

    // ---- RoPE + transposed q/k store ----
    for (int idx = tid; idx < 2048; idx += 256) {
        int p = idx >> 6;     // rope pair 0..31
        int i = idx & 63;     // row in tile
        float x0 = xs[i][4 * p + 0];
        float x1 = xs[i][4 * p + 1];
        float x2 = xs[i][4 * p + 2];
        float x3 = xs[i][4 * p + 3];
        float base = exp2f((float)p * -0.41524101186091903f);
        float fr = (float)(l0 + i) * base;
        float s, c;
        sincosf(fr, &s, &c);
        float q0 = x0 * c - x2 * s;
        float q1 = x0 * s + x2 * c;
        float k0 = x1 * c - x3 * s;
        float k1 = x1 * s + x3 * c;
        int d0 = 2 * p;
        g_qwT[(bb_ * HS + d0) * L_ + l0 + i]     = q0;
        g_qwT[(bb_ * HS + d0 + 1) * L_ + l0 + i] = q1;
        g_kwT[(bb_ * HS + d0) * L_ + l0 + i]     = k0;
        g_kwT[(bb_ * HS + d0 + 1) * L_ + l0 + i] = k1;
    }

    // ---- bias = (x@W2 + b2)/2, stored [b][j][l] ----
    if (tid < 192) {
        int jj = tid % 24;
        int r0 = (tid / 24) * 8;
        float accb[8];
        #pragma unroll
        for (int r = 0; r < 8; r++) accb[r] = 0.f;
        for (int cc = 0; cc < 128; cc++) {
            float w = __ldg(&W2[cc * 24 + jj]);
            #pragma unroll
            for (int r = 0; r < 8; r++) accb[r] += xs[r0 + r][cc] * w;
        }
        float bv2 = __ldg(&b2[jj]);
        #pragma unroll
        for (int r = 0; r < 8; r++)
            g_bias[(bb_ * 24 + jj) * L_ + l0 + r0 + r] = (accb[r] + bv2) * 0.5f;
    }
}

// ---------------------------------------------------------------------------
// Kernel B (unchanged from passing R1): S = q.k^T/8 per 64x64 tile, penalties
// folded once, stream 12 heads. Write-bandwidth bound.
// ---------------------------------------------------------------------------
__global__ __launch_bounds__(256) void logits_kernel(
    const float* __restrict__ am, float* __restrict__ out)
{
    __shared__ __align__(16) float Qt[64][68];
    __shared__ __align__(16) float Kt[64][68];
    __shared__ float brm[12][64];
    __shared__ float bcn[12][64];
    __shared__ float amm[64], amn[64];

    const int b  = blockIdx.z;
    const int m0 = blockIdx.y * 64;
    const int n0 = blockIdx.x * 64;
    const int tid = threadIdx.x;

    #pragma unroll
    for (int f = tid; f < 1024; f += 256) {
        int d = f >> 4, ig = f & 15;
        *(float4*)&Qt[d][ig * 4] = *(const float4*)&g_qwT[(b * HS + d) * L_ + m0 + ig * 4];
        *(float4*)&Kt[d][ig * 4] = *(const float4*)&g_kwT[(b * HS + d) * L_ + n0 + ig * 4];
    }
    #pragma unroll
    for (int f = tid; f < 768; f += 256) {
        int h = f >> 6, i = f & 63;
        brm[h][i] = g_bias[(b * 24 + 2 * h + 1) * L_ + m0 + i];
        bcn[h][i] = g_bias[(b * 24 + 2 * h) * L_ + n0 + i];
    }
    if (tid < 64)       amm[tid]      = am[b * L_ + m0 + tid];
    else if (tid < 128) amn[tid - 64] = am[b * L_ + n0 + tid - 64];
    __syncthreads();

    const int tx = tid & 15;
    const int ty = tid >> 4;

    float acc[4][4];
    #pragma unroll
    for (int r = 0; r < 4; r++)
        #pragma unroll
        for (int c = 0; c < 4; c++) acc[r][c] = 0.f;

    #pragma unroll 16
    for (int d = 0; d < 64; d++) {
        float4 q = *(float4*)&Qt[d][ty * 4];
        float4 k = *(float4*)&Kt[d][tx * 4];
        float qv[4] = {q.x, q.y, q.z, q.w};
        float kv[4] = {k.x, k.y, k.z, k.w};
        #pragma unroll
        for (int r = 0; r < 4; r++)
            #pragma unroll
            for (int c = 0; c < 4; c++)
                acc[r][c] += qv[r] * kv[c];
    }

    float amr[4], amc[4];
    #pragma unroll
    for (int r = 0; r < 4; r++) amr[r] = amm[ty * 4 + r];
    #pragma unroll
    for (int c = 0; c < 4; c++) amc[c] = amn[tx * 4 + c];
    #pragma unroll
    for (int r = 0; r < 4; r++) {
        int m = m0 + ty * 4 + r;
        #pragma unroll
        for (int c = 0; c < 4; c++) {
            int n = n0 + tx * 4 + c;
            float pen = (1.f - amr[r] * amc[c]) * INFV + ((n < m) ? INFV : 0.f);
            acc[r][c] = acc[r][c] * 0.125f - pen;
        }
    }

    const size_t outbase = (size_t)b * NH * L_ * L_ + (size_t)(m0 + ty * 4) * L_ + n0 + tx * 4;
    #pragma unroll
    for (int h = 0; h < NH; h++) {
        float br[4], bc[4];
        #pragma unroll
        for (int r = 0; r < 4; r++) br[r] = brm[h][ty * 4 + r];
        #pragma unroll
        for (int c = 0; c < 4; c++) bc[c] = bcn[h][tx * 4 + c];
        float* op = out + outbase + (size_t)h * L_ * L_;
        #pragma unroll
        for (int r = 0; r < 4; r++) {
            float4 v;
            v.x = acc[r][0] + br[r] + bc[0];
            v.y = acc[r][1] + br[r] + bc[1];
            v.z = acc[r][2] + br[r] + bc[2];
            v.w = acc[r][3] + br[r] + bc[3];
            *(float4*)(op + (size_t)r * L_) = v;
        }
    }
}

// ---------------------------------------------------------------------------
extern "C" void kernel_launch(void* const* d_in, const int* in_sizes, int n_in,
                              void* d_out, int out_size)
{
    const float* inp = (const float*)d_in[0];  // [16,512,1024]
    const float* am  = (const float*)d_in[1];  // [16,512]
    const float* W1  = (const float*)d_in[2];  // [1024,128]
    const float* b1  = (const float*)d_in[3];  // [128]
    const float* W2  = (const float*)d_in[4];  // [128,24]
    const float* b2  = (const float*)d_in[5];  // [24]
    float* out = (float*)d_out;                // [16,12,512,512]

    proj_kernel<<<128, 256>>>(inp, W1, b1, W2, b2);
    dim3 g(8, 8, 16);
    logits_kernel<<<g, 256>>>(am, out);
}

// round 4
// speedup vs baseline: 1.8967x; 1.8967x over previous
#include <cuda_runtime.h>
#include <math.h>
#include <stdint.h>

// Problem constants
#define B_   16
#define L_   512
#define H_   1024
#define HS   64     // HEAD_SIZE
#define NH   12     // HEADS
#define INFV 1000000000000.0f

// Scratch (allocation-free rule: __device__ globals)
__device__ __align__(16) float g_qwT[B_ * HS * L_];          // [b][d][l]
__device__ __align__(16) float g_kwT[B_ * HS * L_];          // [b][d][l]
__device__ __align__(16) float g_bias[B_ * 2 * NH * L_];     // [b][j][l]

// ---------------------------------------------------------------------------
__device__ __forceinline__ void mma_tf32(
    float& c0, float& c1, float& c2, float& c3,
    uint32_t a0, uint32_t a1, uint32_t a2, uint32_t a3,
    uint32_t b0, uint32_t b1)
{
    asm volatile(
        "mma.sync.aligned.m16n8k8.row.col.f32.tf32.tf32.f32 "
        "{%0,%1,%2,%3}, {%4,%5,%6,%7}, {%8,%9}, {%0,%1,%2,%3};"
        : "+f"(c0), "+f"(c1), "+f"(c2), "+f"(c3)
        : "r"(a0), "r"(a1), "r"(a2), "r"(a3), "r"(b0), "r"(b1));
}

__device__ __forceinline__ void cp_async16(uint32_t saddr, const void* gptr) {
    asm volatile("cp.async.cg.shared.global [%0], [%1], 16;" :: "r"(saddr), "l"(gptr));
}
#define CP_COMMIT() asm volatile("cp.async.commit_group;")

// ---------------------------------------------------------------------------
// Kernel A v3: x = inputs@W1 + b1 via TF32 MMA.
//  64(M)x128(N) tile, K-chunk 16, 3-stage cp.async pipeline.
//  Smem: As[3][64][20] (pad 20 -> conflict-free scalar consumer LDS),
//        Bs[3][16][136] (pad 136 -> conflict-free consumer LDS).
//  Stores are coalesced cp.async (conflict-free by construction).
//  Epilogue: RoPE -> g_qwT/g_kwT transposed, bias GEMV -> g_bias.
// grid 128 blocks, 256 threads (8 warps: 2(M) x 4(N)).
// ---------------------------------------------------------------------------
__global__ __launch_bounds__(256) void proj_kernel(
    const float* __restrict__ inp, const float* __restrict__ W1,
    const float* __restrict__ b1,  const float* __restrict__ W2,
    const float* __restrict__ b2)
{
    // pool layout: As stage s at s*1280 (64*20); Bs stage s at 3840 + s*2176 (16*136)
    // total 10368 floats = 41472 B. Reused as xs[64][132] (8448 floats) in epilogue.
    __shared__ __align__(16) float pool[10368];

    const int tid  = threadIdx.x;
    const int lane = tid & 31;
    const int warp = tid >> 5;
    const int wm   = warp >> 2;    // 0..1
    const int wn   = warp & 3;     // 0..3
    const int g    = lane >> 2;    // groupID
    const int t    = lane & 3;     // threadID_in_group
    const int m0   = blockIdx.x * 64;

    const uint32_t smem_base = (uint32_t)__cvta_generic_to_shared(pool);

    // ---- cp.async assignments (per 16-K stage) ----
    // A: 64m x 16k = 256 float4, 1/thread: m=tid>>2, kq=tid&3
    const int am_ = tid >> 2, akq = tid & 3;
    const float* aG = inp + (size_t)(m0 + am_) * H_ + akq * 4;
    const uint32_t a_sts = (uint32_t)(am_ * 20 + akq * 4) * 4;
    // B: 16k x 128n = 512 float4, 2/thread: k=bk0(+8), n=bnq*4
    const int bk0 = tid >> 5, bnq = tid & 31;
    const float* bG0 = W1 + (size_t)bk0 * 128 + bnq * 4;
    const float* bG1 = bG0 + 8 * 128;
    const uint32_t b_sts0 = (uint32_t)(bk0 * 136 + bnq * 4) * 4;
    const uint32_t b_sts1 = (uint32_t)((bk0 + 8) * 136 + bnq * 4) * 4;

    // ---- consumer fragment base offsets (float indices within a stage) ----
    // A(row, col) at row*20+col; a0=(rm+g, k0+t) a1=(+8 row) a2=(+4 col) a3=both
    const int a_base = (wm * 32 + g) * 20 + t;
    // B(k, n) at k*136+n; b0=(k0+t, nb+g) b1=(k0+t+4, nb+g)
    const int b_base = t * 136 + wn * 32 + g;

    float acc[2][4][4];
    #pragma unroll
    for (int mt = 0; mt < 2; mt++)
        #pragma unroll
        for (int nt = 0; nt < 4; nt++)
            #pragma unroll
            for (int c = 0; c < 4; c++) acc[mt][nt][c] = 0.f;

    // ---- prologue: stages 0,1 ----
    #pragma unroll
    for (int s = 0; s < 2; s++) {
        cp_async16(smem_base + s * 5120 + a_sts, aG + s * 16);
        cp_async16(smem_base + 15360 + s * 8704 + b_sts0, bG0 + s * 2048);
        cp_async16(smem_base + 15360 + s * 8704 + b_sts1, bG1 + s * 2048);
        CP_COMMIT();
    }

    int s_c = 0;   // compute stage
    for (int kt = 0; kt < 64; kt++) {
        if (kt < 63) asm volatile("cp.async.wait_group 1;");
        else         asm volatile("cp.async.wait_group 0;");
        __syncthreads();
        if (kt + 2 < 64) {
            int sp = (kt + 2) % 3;
            cp_async16(smem_base + sp * 5120 + a_sts, aG + (kt + 2) * 16);
            cp_async16(smem_base + 15360 + sp * 8704 + b_sts0, bG0 + (size_t)(kt + 2) * 2048);
            cp_async16(smem_base + 15360 + sp * 8704 + b_sts1, bG1 + (size_t)(kt + 2) * 2048);
            CP_COMMIT();
        }
        const float* As = pool + s_c * 1280;
        const float* Bs = pool + 3840 + s_c * 2176;
        #pragma unroll
        for (int ks = 0; ks < 2; ks++) {
            uint32_t af[2][4];
            #pragma unroll
            for (int mt = 0; mt < 2; mt++) {
                int o = a_base + mt * 320 + ks * 8;
                af[mt][0] = __float_as_uint(As[o]);
                af[mt][1] = __float_as_uint(As[o + 160]);
                af[mt][2] = __float_as_uint(As[o + 4]);
                af[mt][3] = __float_as_uint(As[o + 164]);
            }
            uint32_t bf[4][2];
            #pragma unroll
            for (int nt = 0; nt < 4; nt++) {
                int o = b_base + ks * 1088 + nt * 8;
                bf[nt][0] = __float_as_uint(Bs[o]);
                bf[nt][1] = __float_as_uint(Bs[o + 544]);
            }
            #pragma unroll
            for (int mt = 0; mt < 2; mt++)
                #pragma unroll
                for (int nt = 0; nt < 4; nt++)
                    mma_tf32(acc[mt][nt][0], acc[mt][nt][1], acc[mt][nt][2], acc[mt][nt][3],
                             af[mt][0], af[mt][1], af[mt][2], af[mt][3],
                             bf[nt][0], bf[nt][1]);
        }
        s_c = (s_c == 2) ? 0 : s_c + 1;
    }

    __syncthreads();   // all reads of pipeline smem done; reuse pool as xs

    float (*xs)[132] = (float (*)[132])pool;

    // ---- write acc (+b1) into xs ----
    // c0=(g,2t) c1=(g,2t+1) c2=(g+8,2t) c3=(g+8,2t+1)
    #pragma unroll
    for (int mt = 0; mt < 2; mt++) {
        int mrow = wm * 32 + mt * 16 + g;
        #pragma unroll
        for (int nt = 0; nt < 4; nt++) {
            int n = wn * 32 + nt * 8 + t * 2;
            float2 bb = *(const float2*)(b1 + n);
            xs[mrow][n]         = acc[mt][nt][0] + bb.x;
            xs[mrow][n + 1]     = acc[mt][nt][1] + bb.y;
            xs[mrow + 8][n]     = acc[mt][nt][2] + bb.x;
            xs[mrow + 8][n + 1] = acc[mt][nt][3] + bb.y;
        }
    }
    __syncthreads();

    const int bb_ = m0 >> 9;    // batch
    const int l0  = m0 & 511;   // sequence offset of tile

    // ---- RoPE + transposed q/k store ----
    for (int idx = tid; idx < 2048; idx += 256) {
        int p = idx >> 6;     // rope pair 0..31
        int i = idx & 63;     // row in tile
        float x0 = xs[i][4 * p + 0];
        float x1 = xs[i][4 * p + 1];
        float x2 = xs[i][4 * p + 2];
        float x3 = xs[i][4 * p + 3];
        float base = exp2f((float)p * -0.41524101186091903f);
        float fr = (float)(l0 + i) * base;
        float s, c;
        sincosf(fr, &s, &c);
        float q0 = x0 * c - x2 * s;
        float q1 = x0 * s + x2 * c;
        float k0 = x1 * c - x3 * s;
        float k1 = x1 * s + x3 * c;
        int d0 = 2 * p;
        g_qwT[(bb_ * HS + d0) * L_ + l0 + i]     = q0;
        g_qwT[(bb_ * HS + d0 + 1) * L_ + l0 + i] = q1;
        g_kwT[(bb_ * HS + d0) * L_ + l0 + i]     = k0;
        g_kwT[(bb_ * HS + d0 + 1) * L_ + l0 + i] = k1;
    }

    // ---- bias = (x@W2 + b2)/2, stored [b][j][l] ----
    if (tid < 192) {
        int jj = tid % 24;
        int r0 = (tid / 24) * 8;
        float accb[8];
        #pragma unroll
        for (int r = 0; r < 8; r++) accb[r] = 0.f;
        for (int cc = 0; cc < 128; cc++) {
            float w = __ldg(&W2[cc * 24 + jj]);
            #pragma unroll
            for (int r = 0; r < 8; r++) accb[r] += xs[r0 + r][cc] * w;
        }
        float bv2 = __ldg(&b2[jj]);
        #pragma unroll
        for (int r = 0; r < 8; r++)
            g_bias[(bb_ * 24 + jj) * L_ + l0 + r0 + r] = (accb[r] + bv2) * 0.5f;
    }
}

// ---------------------------------------------------------------------------
// Kernel B (byte-identical to passing R1/R3 version)
// ---------------------------------------------------------------------------
__global__ __launch_bounds__(256) void logits_kernel(
    const float* __restrict__ am, float* __restrict__ out)
{
    __shared__ __align__(16) float Qt[64][68];
    __shared__ __align__(16) float Kt[64][68];
    __shared__ float brm[12][64];
    __shared__ float bcn[12][64];
    __shared__ float amm[64], amn[64];

    const int b  = blockIdx.z;
    const int m0 = blockIdx.y * 64;
    const int n0 = blockIdx.x * 64;
    const int tid = threadIdx.x;

    #pragma unroll
    for (int f = tid; f < 1024; f += 256) {
        int d = f >> 4, ig = f & 15;
        *(float4*)&Qt[d][ig * 4] = *(const float4*)&g_qwT[(b * HS + d) * L_ + m0 + ig * 4];
        *(float4*)&Kt[d][ig * 4] = *(const float4*)&g_kwT[(b * HS + d) * L_ + n0 + ig * 4];
    }
    #pragma unroll
    for (int f = tid; f < 768; f += 256) {
        int h = f >> 6, i = f & 63;
        brm[h][i] = g_bias[(b * 24 + 2 * h + 1) * L_ + m0 + i];
        bcn[h][i] = g_bias[(b * 24 + 2 * h) * L_ + n0 + i];
    }
    if (tid < 64)       amm[tid]      = am[b * L_ + m0 + tid];
    else if (tid < 128) amn[tid - 64] = am[b * L_ + n0 + tid - 64];
    __syncthreads();

    const int tx = tid & 15;
    const int ty = tid >> 4;

    float acc[4][4];
    #pragma unroll
    for (int r = 0; r < 4; r++)
        #pragma unroll
        for (int c = 0; c < 4; c++) acc[r][c] = 0.f;

    #pragma unroll 16
    for (int d = 0; d < 64; d++) {
        float4 q = *(float4*)&Qt[d][ty * 4];
        float4 k = *(float4*)&Kt[d][tx * 4];
        float qv[4] = {q.x, q.y, q.z, q.w};
        float kv[4] = {k.x, k.y, k.z, k.w};
        #pragma unroll
        for (int r = 0; r < 4; r++)
            #pragma unroll
            for (int c = 0; c < 4; c++)
                acc[r][c] += qv[r] * kv[c];
    }

    float amr[4], amc[4];
    #pragma unroll
    for (int r = 0; r < 4; r++) amr[r] = amm[ty * 4 + r];
    #pragma unroll
    for (int c = 0; c < 4; c++) amc[c] = amn[tx * 4 + c];
    #pragma unroll
    for (int r = 0; r < 4; r++) {
        int m = m0 + ty * 4 + r;
        #pragma unroll
        for (int c = 0; c < 4; c++) {
            int n = n0 + tx * 4 + c;
            float pen = (1.f - amr[r] * amc[c]) * INFV + ((n < m) ? INFV : 0.f);
            acc[r][c] = acc[r][c] * 0.125f - pen;
        }
    }

    const size_t outbase = (size_t)b * NH * L_ * L_ + (size_t)(m0 + ty * 4) * L_ + n0 + tx * 4;
    #pragma unroll
    for (int h = 0; h < NH; h++) {
        float br[4], bc[4];
        #pragma unroll
        for (int r = 0; r < 4; r++) br[r] = brm[h][ty * 4 + r];
        #pragma unroll
        for (int c = 0; c < 4; c++) bc[c] = bcn[h][tx * 4 + c];
        float* op = out + outbase + (size_t)h * L_ * L_;
        #pragma unroll
        for (int r = 0; r < 4; r++) {
            float4 v;
            v.x = acc[r][0] + br[r] + bc[0];
            v.y = acc[r][1] + br[r] + bc[1];
            v.z = acc[r][2] + br[r] + bc[2];
            v.w = acc[r][3] + br[r] + bc[3];
            *(float4*)(op + (size_t)r * L_) = v;
        }
    }
}

// ---------------------------------------------------------------------------
extern "C" void kernel_launch(void* const* d_in, const int* in_sizes, int n_in,
                              void* d_out, int out_size)
{
    const float* inp = (const float*)d_in[0];  // [16,512,1024]
    const float* am  = (const float*)d_in[1];  // [16,512]
    const float* W1  = (const float*)d_in[2];  // [1024,128]
    const float* b1  = (const float*)d_in[3];  // [128]
    const float* W2  = (const float*)d_in[4];  // [128,24]
    const float* b2  = (const float*)d_in[5];  // [24]
    float* out = (float*)d_out;                // [16,12,512,512]

    proj_kernel<<<128, 256>>>(inp, W1, b1, W2, b2);
    dim3 g(8, 8, 16);
    logits_kernel<<<g, 256>>>(am, out);
}

// round 8
// speedup vs baseline: 1.9017x; 1.0027x over previous
#include <cuda_runtime.h>
#include <math.h>
#include <stdint.h>

// Problem constants
#define B_   16
#define L_   512
#define H_   1024
#define HS   64     // HEAD_SIZE
#define NH   12     // HEADS
#define INFV 1000000000000.0f

// Scratch (allocation-free rule: __device__ globals)
__device__ __align__(16) float g_qwT[B_ * HS * L_];          // [b][d][l]
__device__ __align__(16) float g_kwT[B_ * HS * L_];          // [b][d][l]
__device__ __align__(16) float g_bias[B_ * 2 * NH * L_];     // [b][j][l]

// ---------------------------------------------------------------------------
__device__ __forceinline__ void mma_tf32(
    float& c0, float& c1, float& c2, float& c3,
    uint32_t a0, uint32_t a1, uint32_t a2, uint32_t a3,
    uint32_t b0, uint32_t b1)
{
    asm volatile(
        "mma.sync.aligned.m16n8k8.row.col.f32.tf32.tf32.f32 "
        "{%0,%1,%2,%3}, {%4,%5,%6,%7}, {%8,%9}, {%0,%1,%2,%3};"
        : "+f"(c0), "+f"(c1), "+f"(c2), "+f"(c3)
        : "r"(a0), "r"(a1), "r"(a2), "r"(a3), "r"(b0), "r"(b1));
}

__device__ __forceinline__ void cp_async16(uint32_t saddr, const void* gptr) {
    asm volatile("cp.async.cg.shared.global [%0], [%1], 16;" :: "r"(saddr), "l"(gptr));
}
#define CP_COMMIT() asm volatile("cp.async.commit_group;")

__device__ __forceinline__ void stg_cs_v4(float* p, float x, float y, float z, float w) {
    asm volatile("st.global.cs.v4.f32 [%0], {%1,%2,%3,%4};"
                 :: "l"(p), "f"(x), "f"(y), "f"(z), "f"(w) : "memory");
}

// ---------------------------------------------------------------------------
// Kernel A v4: x = inputs@W1 + b1 via TF32 MMA.
//  32(M)x128(N) tile, K-chunk 16, 3-stage cp.async pipeline, grid 256
//  (≈2 blocks/SM for latency hiding; smem 33.8KB).
//  Smem: As[3][32][20] (conflict-free consumer banks 20g+t),
//        Bs[3][16][136] (conflict-free consumer banks 8t+g).
// 256 threads: 8 warps = 2(M half of 32 rows) x 4(N 32-col slabs).
// ---------------------------------------------------------------------------
__global__ __launch_bounds__(256) void proj_kernel(
    const float* __restrict__ inp, const float* __restrict__ W1,
    const float* __restrict__ b1,  const float* __restrict__ W2,
    const float* __restrict__ b2)
{
    // pool: As stage s at s*640 (32*20); Bs stage s at 1920 + s*2176 (16*136).
    // total 8448 floats = 33792 B. Reused as xs[32][132] (4224) in epilogue.
    __shared__ __align__(16) float pool[8448];

    const int tid  = threadIdx.x;
    const int lane = tid & 31;
    const int warp = tid >> 5;
    const int wm   = warp >> 2;    // 0..1 (16-row half)
    const int wn   = warp & 3;     // 0..3 (32-col slab)
    const int g    = lane >> 2;
    const int t    = lane & 3;
    const int m0   = blockIdx.x * 32;

    const uint32_t smem_base = (uint32_t)__cvta_generic_to_shared(pool);

    // ---- cp.async assignments (per 16-K stage) ----
    // A: 32m x 16k = 128 float4; threads 0..127 only: m=tid>>2, kq=tid&3
    const int am_ = tid >> 2, akq = tid & 3;
    const float* aG = inp + (size_t)(m0 + am_) * H_ + akq * 4;
    const uint32_t a_sts = (uint32_t)(am_ * 20 + akq * 4) * 4;
    const bool do_a = (tid < 128);
    // B: 16k x 128n = 512 float4; 2/thread: f = tid + 256*j, k=f>>5, nq=f&31
    int bk[2], bnq[2];
    #pragma unroll
    for (int j = 0; j < 2; j++) { int f = tid + 256 * j; bk[j] = f >> 5; bnq[j] = f & 31; }
    const float* bG0 = W1 + (size_t)bk[0] * 128 + bnq[0] * 4;
    const float* bG1 = W1 + (size_t)bk[1] * 128 + bnq[1] * 4;
    const uint32_t b_sts0 = (uint32_t)(bk[0] * 136 + bnq[0] * 4) * 4;
    const uint32_t b_sts1 = (uint32_t)(bk[1] * 136 + bnq[1] * 4) * 4;

    // ---- consumer fragment bases (floats within a stage) ----
    const int a_base = (wm * 16 + g) * 20 + t;       // +ks*8; a1=+160, a2=+4, a3=+164
    const int b_base = t * 136 + wn * 32 + g;        // +ks*1088; b1=+544; +nt*8

    float acc[4][4];
    #pragma unroll
    for (int nt = 0; nt < 4; nt++)
        #pragma unroll
        for (int c = 0; c < 4; c++) acc[nt][c] = 0.f;

    // ---- prologue: stages 0,1 ----
    #pragma unroll
    for (int s = 0; s < 2; s++) {
        if (do_a) cp_async16(smem_base + s * 2560 + a_sts, aG + s * 16);
        cp_async16(smem_base + 7680 + s * 8704 + b_sts0, bG0 + s * 2048);
        cp_async16(smem_base + 7680 + s * 8704 + b_sts1, bG1 + s * 2048);
        CP_COMMIT();
    }

    int s_c = 0;
    for (int kt = 0; kt < 64; kt++) {
        if (kt < 63) asm volatile("cp.async.wait_group 1;");
        else         asm volatile("cp.async.wait_group 0;");
        __syncthreads();
        if (kt + 2 < 64) {
            int sp = (kt + 2) % 3;
            if (do_a) cp_async16(smem_base + sp * 2560 + a_sts, aG + (kt + 2) * 16);
            cp_async16(smem_base + 7680 + sp * 8704 + b_sts0, bG0 + (size_t)(kt + 2) * 2048);
            cp_async16(smem_base + 7680 + sp * 8704 + b_sts1, bG1 + (size_t)(kt + 2) * 2048);
            CP_COMMIT();
        }
        const float* As = pool + s_c * 640;
        const float* Bs = pool + 1920 + s_c * 2176;
        #pragma unroll
        for (int ks = 0; ks < 2; ks++) {
            uint32_t a0, a1, a2, a3;
            {
                int o = a_base + ks * 8;
                a0 = __float_as_uint(As[o]);
                a1 = __float_as_uint(As[o + 160]);
                a2 = __float_as_uint(As[o + 4]);
                a3 = __float_as_uint(As[o + 164]);
            }
            uint32_t bf[4][2];
            #pragma unroll
            for (int nt = 0; nt < 4; nt++) {
                int o = b_base + ks * 1088 + nt * 8;
                bf[nt][0] = __float_as_uint(Bs[o]);
                bf[nt][1] = __float_as_uint(Bs[o + 544]);
            }
            #pragma unroll
            for (int nt = 0; nt < 4; nt++)
                mma_tf32(acc[nt][0], acc[nt][1], acc[nt][2], acc[nt][3],
                         a0, a1, a2, a3, bf[nt][0], bf[nt][1]);
        }
        s_c = (s_c == 2) ? 0 : s_c + 1;
    }

    __syncthreads();   // reuse pool as xs

    float (*xs)[132] = (float (*)[132])pool;

    // ---- write acc (+b1) into xs ----
    // c0=(g,2t) c1=(g,2t+1) c2=(g+8,2t) c3=(g+8,2t+1) within 16-row half
    {
        int mrow = wm * 16 + g;
        #pragma unroll
        for (int nt = 0; nt < 4; nt++) {
            int n = wn * 32 + nt * 8 + t * 2;
            float2 bb = *(const float2*)(b1 + n);
            xs[mrow][n]         = acc[nt][0] + bb.x;
            xs[mrow][n + 1]     = acc[nt][1] + bb.y;
            xs[mrow + 8][n]     = acc[nt][2] + bb.x;
            xs[mrow + 8][n + 1] = acc[nt][3] + bb.y;
        }
    }
    __syncthreads();

    const int bb_ = m0 >> 9;
    const int l0  = m0 & 511;

    // ---- RoPE + transposed q/k store (32 rows x 32 pairs = 1024 items) ----
    for (int idx = tid; idx < 1024; idx += 256) {
        int p = idx >> 5;     // rope pair
        int i = idx & 31;     // row in tile
        float x0 = xs[i][4 * p + 0];
        float x1 = xs[i][4 * p + 1];
        float x2 = xs[i][4 * p + 2];
        float x3 = xs[i][4 * p + 3];
        float base = exp2f((float)p * -0.41524101186091903f);
        float fr = (float)(l0 + i) * base;
        float s, c;
        sincosf(fr, &s, &c);
        float q0 = x0 * c - x2 * s;
        float q1 = x0 * s + x2 * c;
        float k0 = x1 * c - x3 * s;
        float k1 = x1 * s + x3 * c;
        int d0 = 2 * p;
        g_qwT[(bb_ * HS + d0) * L_ + l0 + i]     = q0;
        g_qwT[(bb_ * HS + d0 + 1) * L_ + l0 + i] = q1;
        g_kwT[(bb_ * HS + d0) * L_ + l0 + i]     = k0;
        g_kwT[(bb_ * HS + d0 + 1) * L_ + l0 + i] = k1;
    }

    // ---- bias = (x@W2 + b2)/2 ----
    if (tid < 192) {
        int jj = tid % 24;
        int r0 = (tid / 24) * 4;
        float accb[4];
        #pragma unroll
        for (int r = 0; r < 4; r++) accb[r] = 0.f;
        for (int cc = 0; cc < 128; cc++) {
            float w = __ldg(&W2[cc * 24 + jj]);
            #pragma unroll
            for (int r = 0; r < 4; r++) accb[r] += xs[r0 + r][cc] * w;
        }
        float bv2 = __ldg(&b2[jj]);
        #pragma unroll
        for (int r = 0; r < 4; r++)
            g_bias[(bb_ * 24 + jj) * L_ + l0 + r0 + r] = (accb[r] + bv2) * 0.5f;
    }
}

// ---------------------------------------------------------------------------
// Kernel B: same as passing version + streaming (evict-first) output stores.
// ---------------------------------------------------------------------------
__global__ __launch_bounds__(256) void logits_kernel(
    const float* __restrict__ am, float* __restrict__ out)
{
    __shared__ __align__(16) float Qt[64][68];
    __shared__ __align__(16) float Kt[64][68];
    __shared__ float brm[12][64];
    __shared__ float bcn[12][64];
    __shared__ float amm[64], amn[64];

    const int b  = blockIdx.z;
    const int m0 = blockIdx.y * 64;
    const int n0 = blockIdx.x * 64;
    const int tid = threadIdx.x;

    #pragma unroll
    for (int f = tid; f < 1024; f += 256) {
        int d = f >> 4, ig = f & 15;
        *(float4*)&Qt[d][ig * 4] = *(const float4*)&g_qwT[(b * HS + d) * L_ + m0 + ig * 4];
        *(float4*)&Kt[d][ig * 4] = *(const float4*)&g_kwT[(b * HS + d) * L_ + n0 + ig * 4];
    }
    #pragma unroll
    for (int f = tid; f < 768; f += 256) {
        int h = f >> 6, i = f & 63;
        brm[h][i] = g_bias[(b * 24 + 2 * h + 1) * L_ + m0 + i];
        bcn[h][i] = g_bias[(b * 24 + 2 * h) * L_ + n0 + i];
    }
    if (tid < 64)       amm[tid]      = am[b * L_ + m0 + tid];
    else if (tid < 128) amn[tid - 64] = am[b * L_ + n0 + tid - 64];
    __syncthreads();

    const int tx = tid & 15;
    const int ty = tid >> 4;

    float acc[4][4];
    #pragma unroll
    for (int r = 0; r < 4; r++)
        #pragma unroll
        for (int c = 0; c < 4; c++) acc[r][c] = 0.f;

    #pragma unroll 16
    for (int d = 0; d < 64; d++) {
        float4 q = *(float4*)&Qt[d][ty * 4];
        float4 k = *(float4*)&Kt[d][tx * 4];
        float qv[4] = {q.x, q.y, q.z, q.w};
        float kv[4] = {k.x, k.y, k.z, k.w};
        #pragma unroll
        for (int r = 0; r < 4; r++)
            #pragma unroll
            for (int c = 0; c < 4; c++)
                acc[r][c] += qv[r] * kv[c];
    }

    float amr[4], amc[4];
    #pragma unroll
    for (int r = 0; r < 4; r++) amr[r] = amm[ty * 4 + r];
    #pragma unroll
    for (int c = 0; c < 4; c++) amc[c] = amn[tx * 4 + c];
    #pragma unroll
    for (int r = 0; r < 4; r++) {
        int m = m0 + ty * 4 + r;
        #pragma unroll
        for (int c = 0; c < 4; c++) {
            int n = n0 + tx * 4 + c;
            float pen = (1.f - amr[r] * amc[c]) * INFV + ((n < m) ? INFV : 0.f);
            acc[r][c] = acc[r][c] * 0.125f - pen;
        }
    }

    const size_t outbase = (size_t)b * NH * L_ * L_ + (size_t)(m0 + ty * 4) * L_ + n0 + tx * 4;
    #pragma unroll
    for (int h = 0; h < NH; h++) {
        float br[4], bc[4];
        #pragma unroll
        for (int r = 0; r < 4; r++) br[r] = brm[h][ty * 4 + r];
        #pragma unroll
        for (int c = 0; c < 4; c++) bc[c] = bcn[h][tx * 4 + c];
        float* op = out + outbase + (size_t)h * L_ * L_;
        #pragma unroll
        for (int r = 0; r < 4; r++) {
            stg_cs_v4(op + (size_t)r * L_,
                      acc[r][0] + br[r] + bc[0],
                      acc[r][1] + br[r] + bc[1],
                      acc[r][2] + br[r] + bc[2],
                      acc[r][3] + br[r] + bc[3]);
        }
    }
}

// ---------------------------------------------------------------------------
extern "C" void kernel_launch(void* const* d_in, const int* in_sizes, int n_in,
                              void* d_out, int out_size)
{
    const float* inp = (const float*)d_in[0];  // [16,512,1024]
    const float* am  = (const float*)d_in[1];  // [16,512]
    const float* W1  = (const float*)d_in[2];  // [1024,128]
    const float* b1  = (const float*)d_in[3];  // [128]
    const float* W2  = (const float*)d_in[4];  // [128,24]
    const float* b2  = (const float*)d_in[5];  // [24]
    float* out = (float*)d_out;                // [16,12,512,512]

    proj_kernel<<<256, 256>>>(inp, W1, b1, W2, b2);
    dim3 g(8, 8, 16);
    logits_kernel<<<g, 256>>>(am, out);
}

// round 11
// speedup vs baseline: 2.0178x; 1.0610x over previous
#include <cuda_runtime.h>
#include <math.h>
#include <stdint.h>

// Problem constants
#define B_   16
#define L_   512
#define H_   1024
#define HS   64     // HEAD_SIZE
#define NH   12     // HEADS
#define INFV 1000000000000.0f

// Scratch (allocation-free rule: __device__ globals)
__device__ __align__(16) float g_qwT[B_ * HS * L_];          // [b][d][l]
__device__ __align__(16) float g_kwT[B_ * HS * L_];          // [b][d][l]
__device__ __align__(16) float g_bias[B_ * 2 * NH * L_];     // [b][j][l]

// ---------------------------------------------------------------------------
__device__ __forceinline__ void mma_tf32(
    float& c0, float& c1, float& c2, float& c3,
    uint32_t a0, uint32_t a1, uint32_t a2, uint32_t a3,
    uint32_t b0, uint32_t b1)
{
    asm volatile(
        "mma.sync.aligned.m16n8k8.row.col.f32.tf32.tf32.f32 "
        "{%0,%1,%2,%3}, {%4,%5,%6,%7}, {%8,%9}, {%0,%1,%2,%3};"
        : "+f"(c0), "+f"(c1), "+f"(c2), "+f"(c3)
        : "r"(a0), "r"(a1), "r"(a2), "r"(a3), "r"(b0), "r"(b1));
}

__device__ __forceinline__ void cp_async16(uint32_t saddr, const void* gptr) {
    asm volatile("cp.async.cg.shared.global [%0], [%1], 16;" :: "r"(saddr), "l"(gptr));
}
#define CP_COMMIT() asm volatile("cp.async.commit_group;")

// ---------------------------------------------------------------------------
// Kernel A (byte-identical to the R8-passing proj): x = inputs@W1 + b1 via
// TF32 MMA. 32(M)x128(N) tile, K-chunk 16, 3-stage cp.async pipeline,
// grid 256 (2 blocks/SM; smem 33.8KB).
//  Smem: As[3][32][20] (conflict-free consumer banks 20g+t),
//        Bs[3][16][136] (conflict-free consumer banks 8t+g).
// 256 threads: 8 warps = 2(M half of 32 rows) x 4(N 32-col slabs).
// ---------------------------------------------------------------------------
__global__ __launch_bounds__(256) void proj_kernel(
    const float* __restrict__ inp, const float* __restrict__ W1,
    const float* __restrict__ b1,  const float* __restrict__ W2,
    const float* __restrict__ b2)
{
    // pool: As stage s at s*640 (32*20); Bs stage s at 1920 + s*2176 (16*136).
    // total 8448 floats = 33792 B. Reused as xs[32][132] (4224) in epilogue.
    __shared__ __align__(16) float pool[8448];

    const int tid  = threadIdx.x;
    const int lane = tid & 31;
    const int warp = tid >> 5;
    const int wm   = warp >> 2;    // 0..1 (16-row half)
    const int wn   = warp & 3;     // 0..3 (32-col slab)
    const int g    = lane >> 2;
    const int t    = lane & 3;
    const int m0   = blockIdx.x * 32;

    const uint32_t smem_base = (uint32_t)__cvta_generic_to_shared(pool);

    // ---- cp.async assignments (per 16-K stage) ----
    // A: 32m x 16k = 128 float4; threads 0..127 only: m=tid>>2, kq=tid&3
    const int am_ = tid >> 2, akq = tid & 3;
    const float* aG = inp + (size_t)(m0 + am_) * H_ + akq * 4;
    const uint32_t a_sts = (uint32_t)(am_ * 20 + akq * 4) * 4;
    const bool do_a = (tid < 128);
    // B: 16k x 128n = 512 float4; 2/thread: f = tid + 256*j, k=f>>5, nq=f&31
    int bk[2], bnq[2];
    #pragma unroll
    for (int j = 0; j < 2; j++) { int f = tid + 256 * j; bk[j] = f >> 5; bnq[j] = f & 31; }
    const float* bG0 = W1 + (size_t)bk[0] * 128 + bnq[0] * 4;
    const float* bG1 = W1 + (size_t)bk[1] * 128 + bnq[1] * 4;
    const uint32_t b_sts0 = (uint32_t)(bk[0] * 136 + bnq[0] * 4) * 4;
    const uint32_t b_sts1 = (uint32_t)(bk[1] * 136 + bnq[1] * 4) * 4;

    // ---- consumer fragment bases (floats within a stage) ----
    const int a_base = (wm * 16 + g) * 20 + t;       // +ks*8; a1=+160, a2=+4, a3=+164
    const int b_base = t * 136 + wn * 32 + g;        // +ks*1088; b1=+544; +nt*8

    float acc[4][4];
    #pragma unroll
    for (int nt = 0; nt < 4; nt++)
        #pragma unroll
        for (int c = 0; c < 4; c++) acc[nt][c] = 0.f;

    // ---- prologue: stages 0,1 ----
    #pragma unroll
    for (int s = 0; s < 2; s++) {
        if (do_a) cp_async16(smem_base + s * 2560 + a_sts, aG + s * 16);
        cp_async16(smem_base + 7680 + s * 8704 + b_sts0, bG0 + s * 2048);
        cp_async16(smem_base + 7680 + s * 8704 + b_sts1, bG1 + s * 2048);
        CP_COMMIT();
    }

    int s_c = 0;
    for (int kt = 0; kt < 64; kt++) {
        if (kt < 63) asm volatile("cp.async.wait_group 1;");
        else         asm volatile("cp.async.wait_group 0;");
        __syncthreads();
        if (kt + 2 < 64) {
            int sp = (kt + 2) % 3;
            if (do_a) cp_async16(smem_base + sp * 2560 + a_sts, aG + (kt + 2) * 16);
            cp_async16(smem_base + 7680 + sp * 8704 + b_sts0, bG0 + (size_t)(kt + 2) * 2048);
            cp_async16(smem_base + 7680 + sp * 8704 + b_sts1, bG1 + (size_t)(kt + 2) * 2048);
            CP_COMMIT();
        }
        const float* As = pool + s_c * 640;
        const float* Bs = pool + 1920 + s_c * 2176;
        #pragma unroll
        for (int ks = 0; ks < 2; ks++) {
            uint32_t a0, a1, a2, a3;
            {
                int o = a_base + ks * 8;
                a0 = __float_as_uint(As[o]);
                a1 = __float_as_uint(As[o + 160]);
                a2 = __float_as_uint(As[o + 4]);
                a3 = __float_as_uint(As[o + 164]);
            }
            uint32_t bf[4][2];
            #pragma unroll
            for (int nt = 0; nt < 4; nt++) {
                int o = b_base + ks * 1088 + nt * 8;
                bf[nt][0] = __float_as_uint(Bs[o]);
                bf[nt][1] = __float_as_uint(Bs[o + 544]);
            }
            #pragma unroll
            for (int nt = 0; nt < 4; nt++)
                mma_tf32(acc[nt][0], acc[nt][1], acc[nt][2], acc[nt][3],
                         a0, a1, a2, a3, bf[nt][0], bf[nt][1]);
        }
        s_c = (s_c == 2) ? 0 : s_c + 1;
    }

    __syncthreads();   // reuse pool as xs

    float (*xs)[132] = (float (*)[132])pool;

    // ---- write acc (+b1) into xs ----
    // c0=(g,2t) c1=(g,2t+1) c2=(g+8,2t) c3=(g+8,2t+1) within 16-row half
    {
        int mrow = wm * 16 + g;
        #pragma unroll
        for (int nt = 0; nt < 4; nt++) {
            int n = wn * 32 + nt * 8 + t * 2;
            float2 bb = *(const float2*)(b1 + n);
            xs[mrow][n]         = acc[nt][0] + bb.x;
            xs[mrow][n + 1]     = acc[nt][1] + bb.y;
            xs[mrow + 8][n]     = acc[nt][2] + bb.x;
            xs[mrow + 8][n + 1] = acc[nt][3] + bb.y;
        }
    }
    __syncthreads();

    const int bb_ = m0 >> 9;
    const int l0  = m0 & 511;

    // ---- RoPE + transposed q/k store (32 rows x 32 pairs = 1024 items) ----
    for (int idx = tid; idx < 1024; idx += 256) {
        int p = idx >> 5;     // rope pair
        int i = idx & 31;     // row in tile
        float x0 = xs[i][4 * p + 0];
        float x1 = xs[i][4 * p + 1];
        float x2 = xs[i][4 * p + 2];
        float x3 = xs[i][4 * p + 3];
        float base = exp2f((float)p * -0.41524101186091903f);
        float fr = (float)(l0 + i) * base;
        float s, c;
        sincosf(fr, &s, &c);
        float q0 = x0 * c - x2 * s;
        float q1 = x0 * s + x2 * c;
        float k0 = x1 * c - x3 * s;
        float k1 = x1 * s + x3 * c;
        int d0 = 2 * p;
        g_qwT[(bb_ * HS + d0) * L_ + l0 + i]     = q0;
        g_qwT[(bb_ * HS + d0 + 1) * L_ + l0 + i] = q1;
        g_kwT[(bb_ * HS + d0) * L_ + l0 + i]     = k0;
        g_kwT[(bb_ * HS + d0 + 1) * L_ + l0 + i] = k1;
    }

    // ---- bias = (x@W2 + b2)/2 ----
    if (tid < 192) {
        int jj = tid % 24;
        int r0 = (tid / 24) * 4;
        float accb[4];
        #pragma unroll
        for (int r = 0; r < 4; r++) accb[r] = 0.f;
        for (int cc = 0; cc < 128; cc++) {
            float w = __ldg(&W2[cc * 24 + jj]);
            #pragma unroll
            for (int r = 0; r < 4; r++) accb[r] += xs[r0 + r][cc] * w;
        }
        float bv2 = __ldg(&b2[jj]);
        #pragma unroll
        for (int r = 0; r < 4; r++)
            g_bias[(bb_ * 24 + jj) * L_ + l0 + r0 + r] = (accb[r] + bv2) * 0.5f;
    }
}

// ---------------------------------------------------------------------------
// Kernel B (byte-identical to the R4-passing logits: plain float4 stores).
// ---------------------------------------------------------------------------
__global__ __launch_bounds__(256) void logits_kernel(
    const float* __restrict__ am, float* __restrict__ out)
{
    __shared__ __align__(16) float Qt[64][68];
    __shared__ __align__(16) float Kt[64][68];
    __shared__ float brm[12][64];
    __shared__ float bcn[12][64];
    __shared__ float amm[64], amn[64];

    const int b  = blockIdx.z;
    const int m0 = blockIdx.y * 64;
    const int n0 = blockIdx.x * 64;
    const int tid = threadIdx.x;

    #pragma unroll
    for (int f = tid; f < 1024; f += 256) {
        int d = f >> 4, ig = f & 15;
        *(float4*)&Qt[d][ig * 4] = *(const float4*)&g_qwT[(b * HS + d) * L_ + m0 + ig * 4];
        *(float4*)&Kt[d][ig * 4] = *(const float4*)&g_kwT[(b * HS + d) * L_ + n0 + ig * 4];
    }
    #pragma unroll
    for (int f = tid; f < 768; f += 256) {
        int h = f >> 6, i = f & 63;
        brm[h][i] = g_bias[(b * 24 + 2 * h + 1) * L_ + m0 + i];
        bcn[h][i] = g_bias[(b * 24 + 2 * h) * L_ + n0 + i];
    }
    if (tid < 64)       amm[tid]      = am[b * L_ + m0 + tid];
    else if (tid < 128) amn[tid - 64] = am[b * L_ + n0 + tid - 64];
    __syncthreads();

    const int tx = tid & 15;
    const int ty = tid >> 4;

    float acc[4][4];
    #pragma unroll
    for (int r = 0; r < 4; r++)
        #pragma unroll
        for (int c = 0; c < 4; c++) acc[r][c] = 0.f;

    #pragma unroll 16
    for (int d = 0; d < 64; d++) {
        float4 q = *(float4*)&Qt[d][ty * 4];
        float4 k = *(float4*)&Kt[d][tx * 4];
        float qv[4] = {q.x, q.y, q.z, q.w};
        float kv[4] = {k.x, k.y, k.z, k.w};
        #pragma unroll
        for (int r = 0; r < 4; r++)
            #pragma unroll
            for (int c = 0; c < 4; c++)
                acc[r][c] += qv[r] * kv[c];
    }

    float amr[4], amc[4];
    #pragma unroll
    for (int r = 0; r < 4; r++) amr[r] = amm[ty * 4 + r];
    #pragma unroll
    for (int c = 0; c < 4; c++) amc[c] = amn[tx * 4 + c];
    #pragma unroll
    for (int r = 0; r < 4; r++) {
        int m = m0 + ty * 4 + r;
        #pragma unroll
        for (int c = 0; c < 4; c++) {
            int n = n0 + tx * 4 + c;
            float pen = (1.f - amr[r] * amc[c]) * INFV + ((n < m) ? INFV : 0.f);
            acc[r][c] = acc[r][c] * 0.125f - pen;
        }
    }

    const size_t outbase = (size_t)b * NH * L_ * L_ + (size_t)(m0 + ty * 4) * L_ + n0 + tx * 4;
    #pragma unroll
    for (int h = 0; h < NH; h++) {
        float br[4], bc[4];
        #pragma unroll
        for (int r = 0; r < 4; r++) br[r] = brm[h][ty * 4 + r];
        #pragma unroll
        for (int c = 0; c < 4; c++) bc[c] = bcn[h][tx * 4 + c];
        float* op = out + outbase + (size_t)h * L_ * L_;
        #pragma unroll
        for (int r = 0; r < 4; r++) {
            float4 v;
            v.x = acc[r][0] + br[r] + bc[0];
            v.y = acc[r][1] + br[r] + bc[1];
            v.z = acc[r][2] + br[r] + bc[2];
            v.w = acc[r][3] + br[r] + bc[3];
            *(float4*)(op + (size_t)r * L_) = v;
        }
    }
}

// ---------------------------------------------------------------------------
extern "C" void kernel_launch(void* const* d_in, const int* in_sizes, int n_in,
                              void* d_out, int out_size)
{
    const float* inp = (const float*)d_in[0];  // [16,512,1024]
    const float* am  = (const float*)d_in[1];  // [16,512]
    const float* W1  = (const float*)d_in[2];  // [1024,128]
    const float* b1  = (const float*)d_in[3];  // [128]
    const float* W2  = (const float*)d_in[4];  // [128,24]
    const float* b2  = (const float*)d_in[5];  // [24]
    float* out = (float*)d_out;                // [16,12,512,512]

    proj_kernel<<<256, 256>>>(inp, W1, b1, W2, b2);
    dim3 g(8, 8, 16);
    logits_kernel<<<g, 256>>>(am, out);
}

// round 12
// speedup vs baseline: 2.1081x; 1.0448x over previous
#include <cuda_runtime.h>
#include <math.h>
#include <stdint.h>

// Problem constants
#define B_   16
#define L_   512
#define H_   1024
#define HS   64     // HEAD_SIZE
#define NH   12     // HEADS
#define INFV 1000000000000.0f

// Scratch (allocation-free rule: __device__ globals)
__device__ __align__(16) float g_qwT[B_ * HS * L_];          // [b][d][l]
__device__ __align__(16) float g_kwT[B_ * HS * L_];          // [b][d][l]
__device__ __align__(16) float g_bias[B_ * 2 * NH * L_];     // [b][j][l]

#define NSTAGE 4
#define AS_FLOATS 640          // 32*20 per stage
#define BS_FLOATS 2176         // 16*136 per stage
#define BS_BASE   (NSTAGE * AS_FLOATS)          // 2560 floats
#define POOL_FLOATS (BS_BASE + NSTAGE * BS_FLOATS)  // 11264 floats = 45056 B

// ---------------------------------------------------------------------------
__device__ __forceinline__ void mma_tf32(
    float& c0, float& c1, float& c2, float& c3,
    uint32_t a0, uint32_t a1, uint32_t a2, uint32_t a3,
    uint32_t b0, uint32_t b1)
{
    asm volatile(
        "mma.sync.aligned.m16n8k8.row.col.f32.tf32.tf32.f32 "
        "{%0,%1,%2,%3}, {%4,%5,%6,%7}, {%8,%9}, {%0,%1,%2,%3};"
        : "+f"(c0), "+f"(c1), "+f"(c2), "+f"(c3)
        : "r"(a0), "r"(a1), "r"(a2), "r"(a3), "r"(b0), "r"(b1));
}

__device__ __forceinline__ void cp_async16(uint32_t saddr, const void* gptr) {
    asm volatile("cp.async.cg.shared.global [%0], [%1], 16;" :: "r"(saddr), "l"(gptr));
}
#define CP_COMMIT() asm volatile("cp.async.commit_group;")

// Issue one 16-K stage of cp.async copies (A: 128 f4 by threads<128; B: 512 f4).
__device__ __forceinline__ void issue_stage(
    int stage, int ktile, bool do_a,
    uint32_t smem_base, uint32_t a_sts, uint32_t b_sts0, uint32_t b_sts1,
    const float* aG, const float* bG0, const float* bG1)
{
    if (do_a)
        cp_async16(smem_base + (uint32_t)stage * (AS_FLOATS * 4) + a_sts,
                   aG + ktile * 16);
    const uint32_t bbase = smem_base + BS_BASE * 4 + (uint32_t)stage * (BS_FLOATS * 4);
    cp_async16(bbase + b_sts0, bG0 + (size_t)ktile * 2048);
    cp_async16(bbase + b_sts1, bG1 + (size_t)ktile * 2048);
    CP_COMMIT();
}

// ---------------------------------------------------------------------------
// Kernel A v6: x = inputs@W1 + b1 via TF32 MMA.
//  32(M)x128(N) tile, K-chunk 16, 4-stage cp.async pipeline (wait_group 2 =>
//  stage consumed 3 iterations after issue, ~600+cyc lead > 577cyc DRAM
//  latency), grid 256, smem 45KB -> 2 blocks/SM.
//  Smem: As[4][32][20] (conflict-free consumer banks 20g+t),
//        Bs[4][16][136] (conflict-free consumer banks 8t+g).
// 256 threads: 8 warps = 2(M half) x 4(N 32-col slabs).
// ---------------------------------------------------------------------------
__global__ __launch_bounds__(256) void proj_kernel(
    const float* __restrict__ inp, const float* __restrict__ W1,
    const float* __restrict__ b1,  const float* __restrict__ W2,
    const float* __restrict__ b2)
{
    __shared__ __align__(16) float pool[POOL_FLOATS];  // epilogue reuses as xs[32][132]

    const int tid  = threadIdx.x;
    const int lane = tid & 31;
    const int warp = tid >> 5;
    const int wm   = warp >> 2;    // 0..1 (16-row half)
    const int wn   = warp & 3;     // 0..3 (32-col slab)
    const int g    = lane >> 2;
    const int t    = lane & 3;
    const int m0   = blockIdx.x * 32;

    const uint32_t smem_base = (uint32_t)__cvta_generic_to_shared(pool);

    // ---- cp.async assignments (per 16-K stage) ----
    const int am_ = tid >> 2, akq = tid & 3;
    const float* aG = inp + (size_t)(m0 + am_) * H_ + akq * 4;
    const uint32_t a_sts = (uint32_t)(am_ * 20 + akq * 4) * 4;
    const bool do_a = (tid < 128);
    int bk[2], bnq[2];
    #pragma unroll
    for (int j = 0; j < 2; j++) { int f = tid + 256 * j; bk[j] = f >> 5; bnq[j] = f & 31; }
    const float* bG0 = W1 + (size_t)bk[0] * 128 + bnq[0] * 4;
    const float* bG1 = W1 + (size_t)bk[1] * 128 + bnq[1] * 4;
    const uint32_t b_sts0 = (uint32_t)(bk[0] * 136 + bnq[0] * 4) * 4;
    const uint32_t b_sts1 = (uint32_t)(bk[1] * 136 + bnq[1] * 4) * 4;

    // ---- consumer fragment bases (floats within a stage) ----
    const int a_base = (wm * 16 + g) * 20 + t;       // +ks*8; a1=+160, a2=+4, a3=+164
    const int b_base = t * 136 + wn * 32 + g;        // +ks*1088; b1=+544; +nt*8

    float acc[4][4];
    #pragma unroll
    for (int nt = 0; nt < 4; nt++)
        #pragma unroll
        for (int c = 0; c < 4; c++) acc[nt][c] = 0.f;

    // ---- prologue: stages 0..2 ----
    #pragma unroll
    for (int s = 0; s < NSTAGE - 1; s++)
        issue_stage(s, s, do_a, smem_base, a_sts, b_sts0, b_sts1, aG, bG0, bG1);

    int s_c = 0;
    for (int kt = 0; kt < 64; kt++) {
        // complete stage kt: pending before wait is min(3, 64-kt)
        if (kt < 62)       asm volatile("cp.async.wait_group 2;");
        else if (kt == 62) asm volatile("cp.async.wait_group 1;");
        else               asm volatile("cp.async.wait_group 0;");
        __syncthreads();
        if (kt + NSTAGE - 1 < 64)
            issue_stage((kt + NSTAGE - 1) & (NSTAGE - 1), kt + NSTAGE - 1, do_a,
                        smem_base, a_sts, b_sts0, b_sts1, aG, bG0, bG1);

        const float* As = pool + s_c * AS_FLOATS;
        const float* Bs = pool + BS_BASE + s_c * BS_FLOATS;
        #pragma unroll
        for (int ks = 0; ks < 2; ks++) {
            uint32_t a0, a1, a2, a3;
            {
                int o = a_base + ks * 8;
                a0 = __float_as_uint(As[o]);
                a1 = __float_as_uint(As[o + 160]);
                a2 = __float_as_uint(As[o + 4]);
                a3 = __float_as_uint(As[o + 164]);
            }
            uint32_t bf[4][2];
            #pragma unroll
            for (int nt = 0; nt < 4; nt++) {
                int o = b_base + ks * 1088 + nt * 8;
                bf[nt][0] = __float_as_uint(Bs[o]);
                bf[nt][1] = __float_as_uint(Bs[o + 544]);
            }
            #pragma unroll
            for (int nt = 0; nt < 4; nt++)
                mma_tf32(acc[nt][0], acc[nt][1], acc[nt][2], acc[nt][3],
                         a0, a1, a2, a3, bf[nt][0], bf[nt][1]);
        }
        s_c = (s_c + 1) & (NSTAGE - 1);
    }

    __syncthreads();   // reuse pool as xs

    float (*xs)[132] = (float (*)[132])pool;

    // ---- write acc (+b1) into xs ----
    {
        int mrow = wm * 16 + g;
        #pragma unroll
        for (int nt = 0; nt < 4; nt++) {
            int n = wn * 32 + nt * 8 + t * 2;
            float2 bb = *(const float2*)(b1 + n);
            xs[mrow][n]         = acc[nt][0] + bb.x;
            xs[mrow][n + 1]     = acc[nt][1] + bb.y;
            xs[mrow + 8][n]     = acc[nt][2] + bb.x;
            xs[mrow + 8][n + 1] = acc[nt][3] + bb.y;
        }
    }
    __syncthreads();

    const int bb_ = m0 >> 9;
    const int l0  = m0 & 511;

    // ---- RoPE + transposed q/k store ----
    for (int idx = tid; idx < 1024; idx += 256) {
        int p = idx >> 5;     // rope pair
        int i = idx & 31;     // row in tile
        float x0 = xs[i][4 * p + 0];
        float x1 = xs[i][4 * p + 1];
        float x2 = xs[i][4 * p + 2];
        float x3 = xs[i][4 * p + 3];
        float base = exp2f((float)p * -0.41524101186091903f);
        float fr = (float)(l0 + i) * base;
        float s, c;
        sincosf(fr, &s, &c);
        float q0 = x0 * c - x2 * s;
        float q1 = x0 * s + x2 * c;
        float k0 = x1 * c - x3 * s;
        float k1 = x1 * s + x3 * c;
        int d0 = 2 * p;
        g_qwT[(bb_ * HS + d0) * L_ + l0 + i]     = q0;
        g_qwT[(bb_ * HS + d0 + 1) * L_ + l0 + i] = q1;
        g_kwT[(bb_ * HS + d0) * L_ + l0 + i]     = k0;
        g_kwT[(bb_ * HS + d0 + 1) * L_ + l0 + i] = k1;
    }

    // ---- bias = (x@W2 + b2)/2 ----
    if (tid < 192) {
        int jj = tid % 24;
        int r0 = (tid / 24) * 4;
        float accb[4];
        #pragma unroll
        for (int r = 0; r < 4; r++) accb[r] = 0.f;
        for (int cc = 0; cc < 128; cc++) {
            float w = __ldg(&W2[cc * 24 + jj]);
            #pragma unroll
            for (int r = 0; r < 4; r++) accb[r] += xs[r0 + r][cc] * w;
        }
        float bv2 = __ldg(&b2[jj]);
        #pragma unroll
        for (int r = 0; r < 4; r++)
            g_bias[(bb_ * 24 + jj) * L_ + l0 + r0 + r] = (accb[r] + bv2) * 0.5f;
    }
}

// ---------------------------------------------------------------------------
// Kernel B (byte-identical to the R11-passing logits, 38.3us measured).
// ---------------------------------------------------------------------------
__global__ __launch_bounds__(256) void logits_kernel(
    const float* __restrict__ am, float* __restrict__ out)
{
    __shared__ __align__(16) float Qt[64][68];
    __shared__ __align__(16) float Kt[64][68];
    __shared__ float brm[12][64];
    __shared__ float bcn[12][64];
    __shared__ float amm[64], amn[64];

    const int b  = blockIdx.z;
    const int m0 = blockIdx.y * 64;
    const int n0 = blockIdx.x * 64;
    const int tid = threadIdx.x;

    #pragma unroll
    for (int f = tid; f < 1024; f += 256) {
        int d = f >> 4, ig = f & 15;
        *(float4*)&Qt[d][ig * 4] = *(const float4*)&g_qwT[(b * HS + d) * L_ + m0 + ig * 4];
        *(float4*)&Kt[d][ig * 4] = *(const float4*)&g_kwT[(b * HS + d) * L_ + n0 + ig * 4];
    }
    #pragma unroll
    for (int f = tid; f < 768; f += 256) {
        int h = f >> 6, i = f & 63;
        brm[h][i] = g_bias[(b * 24 + 2 * h + 1) * L_ + m0 + i];
        bcn[h][i] = g_bias[(b * 24 + 2 * h) * L_ + n0 + i];
    }
    if (tid < 64)       amm[tid]      = am[b * L_ + m0 + tid];
    else if (tid < 128) amn[tid - 64] = am[b * L_ + n0 + tid - 64];
    __syncthreads();

    const int tx = tid & 15;
    const int ty = tid >> 4;

    float acc[4][4];
    #pragma unroll
    for (int r = 0; r < 4; r++)
        #pragma unroll
        for (int c = 0; c < 4; c++) acc[r][c] = 0.f;

    #pragma unroll 16
    for (int d = 0; d < 64; d++) {
        float4 q = *(float4*)&Qt[d][ty * 4];
        float4 k = *(float4*)&Kt[d][tx * 4];
        float qv[4] = {q.x, q.y, q.z, q.w};
        float kv[4] = {k.x, k.y, k.z, k.w};
        #pragma unroll
        for (int r = 0; r < 4; r++)
            #pragma unroll
            for (int c = 0; c < 4; c++)
                acc[r][c] += qv[r] * kv[c];
    }

    float amr[4], amc[4];
    #pragma unroll
    for (int r = 0; r < 4; r++) amr[r] = amm[ty * 4 + r];
    #pragma unroll
    for (int c = 0; c < 4; c++) amc[c] = amn[tx * 4 + c];
    #pragma unroll
    for (int r = 0; r < 4; r++) {
        int m = m0 + ty * 4 + r;
        #pragma unroll
        for (int c = 0; c < 4; c++) {
            int n = n0 + tx * 4 + c;
            float pen = (1.f - amr[r] * amc[c]) * INFV + ((n < m) ? INFV : 0.f);
            acc[r][c] = acc[r][c] * 0.125f - pen;
        }
    }

    const size_t outbase = (size_t)b * NH * L_ * L_ + (size_t)(m0 + ty * 4) * L_ + n0 + tx * 4;
    #pragma unroll
    for (int h = 0; h < NH; h++) {
        float br[4], bc[4];
        #pragma unroll
        for (int r = 0; r < 4; r++) br[r] = brm[h][ty * 4 + r];
        #pragma unroll
        for (int c = 0; c < 4; c++) bc[c] = bcn[h][tx * 4 + c];
        float* op = out + outbase + (size_t)h * L_ * L_;
        #pragma unroll
        for (int r = 0; r < 4; r++) {
            float4 v;
            v.x = acc[r][0] + br[r] + bc[0];
            v.y = acc[r][1] + br[r] + bc[1];
            v.z = acc[r][2] + br[r] + bc[2];
            v.w = acc[r][3] + br[r] + bc[3];
            *(float4*)(op + (size_t)r * L_) = v;
        }
    }
}

// ---------------------------------------------------------------------------
extern "C" void kernel_launch(void* const* d_in, const int* in_sizes, int n_in,
                              void* d_out, int out_size)
{
    const float* inp = (const float*)d_in[0];  // [16,512,1024]
    const float* am  = (const float*)d_in[1];  // [16,512]
    const float* W1  = (const float*)d_in[2];  // [1024,128]
    const float* b1  = (const float*)d_in[3];  // [128]
    const float* W2  = (const float*)d_in[4];  // [128,24]
    const float* b2  = (const float*)d_in[5];  // [24]
    float* out = (float*)d_out;                // [16,12,512,512]

    proj_kernel<<<256, 256>>>(inp, W1, b1, W2, b2);
    dim3 g(8, 8, 16);
    logits_kernel<<<g, 256>>>(am, out);
}